// round 1
// baseline (speedup 1.0000x reference)
#include <cuda_runtime.h>

// ---------------------------------------------------------------------------
// BetterGCN: 2-layer GCN (GCNConv -> BN -> ReLU -> PairNorm -> +residual proj)
// Fixed shapes from the reference.
// ---------------------------------------------------------------------------
#define NN    50000
#define EE    800000
#define TOTE  (EE + NN)
#define IND   500
#define H1D   512
#define H2D   256
#define BN_EPSF 1e-5f
#define PN_EPSF 1e-12f

#define SCAN_CH 64
#define SCAN_NB ((NN + SCAN_CH - 1) / SCAN_CH)   // 782 (<=1024 for 2nd level)

// ------------------------- device scratch (no allocs) ----------------------
__device__ float g_xw[(size_t)NN * H1D];   // x@W (L1) / h1@W2 (L2)
__device__ float g_xp[(size_t)NN * H1D];   // x@P1w+P1b / h1@P2w+P2b
__device__ float g_h [(size_t)NN * H1D];   // h1pre -> h1 (in place)

__device__ int   g_cnt[NN];
__device__ float g_dinv[NN];
__device__ int   g_off[NN + 1];
__device__ int   g_cur[NN];
__device__ int   g_csr[TOTE];
__device__ int   g_part[1024];

__device__ float g_colsum[H1D], g_colsumsq[H1D];
__device__ float g_bna[H1D], g_bnb[H1D];        // folded BN scale/shift
__device__ float g_pnsum[H1D], g_pnmean[H1D];
__device__ float g_sumsqtot;
__device__ float g_invd;

// ------------------------------- CSR build ---------------------------------
__global__ void k_init() {
    int i = blockIdx.x * blockDim.x + threadIdx.x;
    if (i < NN) g_cnt[i] = 1;                     // self loop
    if (i < H1D) {
        g_colsum[i] = 0.f; g_colsumsq[i] = 0.f; g_pnsum[i] = 0.f;
    }
    if (i == 0) { g_sumsqtot = 0.f; }
}

__global__ void k_count(const int* __restrict__ dst) {
    int e = blockIdx.x * blockDim.x + threadIdx.x;
    if (e < EE) atomicAdd(&g_cnt[dst[e]], 1);
}

__global__ void k_dinv() {
    int i = blockIdx.x * blockDim.x + threadIdx.x;
    if (i < NN) g_dinv[i] = rsqrtf((float)g_cnt[i]);
}

__global__ void k_scan1() {
    __shared__ int s[SCAN_CH];
    int b = blockIdx.x, t = threadIdx.x;
    int i = b * SCAN_CH + t;
    int v = (i < NN) ? g_cnt[i] : 0;
    s[t] = v; __syncthreads();
    for (int o = 1; o < SCAN_CH; o <<= 1) {
        int u = (t >= o) ? s[t - o] : 0;
        __syncthreads();
        s[t] += u;
        __syncthreads();
    }
    if (i < NN) g_off[i] = s[t] - v;              // exclusive within chunk
    if (t == SCAN_CH - 1) g_part[b] = s[t];
}

__global__ void k_scan2() {
    __shared__ int s[1024];
    int t = threadIdx.x;
    int v = (t < SCAN_NB) ? g_part[t] : 0;
    s[t] = v; __syncthreads();
    for (int o = 1; o < 1024; o <<= 1) {
        int u = (t >= o) ? s[t - o] : 0;
        __syncthreads();
        s[t] += u;
        __syncthreads();
    }
    if (t < SCAN_NB) g_part[t] = s[t] - v;        // exclusive chunk bases
    if (t == SCAN_NB - 1) g_off[NN] = s[t];       // total = E + N
}

__global__ void k_scan3() {
    int b = blockIdx.x, t = threadIdx.x;
    int i = b * SCAN_CH + t;
    if (i < NN) {
        int o = g_off[i] + g_part[b];
        g_off[i] = o;
        g_cur[i] = o;
    }
}

__global__ void k_fill(const int* __restrict__ src, const int* __restrict__ dst) {
    int t = blockIdx.x * blockDim.x + threadIdx.x;
    if (t >= TOTE) return;
    int s, d;
    if (t < EE) { s = src[t]; d = dst[t]; }
    else        { s = t - EE; d = s; }
    int slot = atomicAdd(&g_cur[d], 1);
    g_csr[slot] = s;
}

// ------------------------------ SGEMM (fp32) -------------------------------
// C[M,N] = A[M,K] @ B[K,N] (+bias). 128x128 tile, BK=8, 256 thr, 8x8/thread.
__global__ __launch_bounds__(256)
void k_sgemm(const float* __restrict__ A, const float* __restrict__ B,
             const float* __restrict__ bias, float* __restrict__ C,
             int M, int N, int K) {
    __shared__ float As[8][128];
    __shared__ float Bs[8][128];
    int tid = threadIdx.x;
    int tx = tid & 15, ty = tid >> 4;
    int row0 = blockIdx.y * 128, col0 = blockIdx.x * 128;

    float acc[8][8];
#pragma unroll
    for (int i = 0; i < 8; i++)
#pragma unroll
        for (int j = 0; j < 8; j++) acc[i][j] = 0.f;

    int aRow = tid >> 1;            // 0..127
    int aCol = (tid & 1) * 4;       // 0 or 4
    int bRow = tid >> 5;            // 0..7
    int bCol = (tid & 31) * 4;      // 0..124

    for (int k0 = 0; k0 < K; k0 += 8) {
        // A tile (transposed in smem)
        float4 av = make_float4(0.f, 0.f, 0.f, 0.f);
        int gm = row0 + aRow;
        if (gm < M) {
            int gk = k0 + aCol;
            if (gk + 3 < K) {
                av = *(const float4*)(A + (size_t)gm * K + gk);
            } else {
                float tmp[4] = {0.f, 0.f, 0.f, 0.f};
#pragma unroll
                for (int x = 0; x < 4; x++)
                    if (gk + x < K) tmp[x] = A[(size_t)gm * K + gk + x];
                av = make_float4(tmp[0], tmp[1], tmp[2], tmp[3]);
            }
        }
        As[aCol + 0][aRow] = av.x;
        As[aCol + 1][aRow] = av.y;
        As[aCol + 2][aRow] = av.z;
        As[aCol + 3][aRow] = av.w;

        // B tile
        int gk = k0 + bRow;
        float4 bv = make_float4(0.f, 0.f, 0.f, 0.f);
        if (gk < K) bv = *(const float4*)(B + (size_t)gk * N + col0 + bCol);
        *(float4*)&Bs[bRow][bCol] = bv;

        __syncthreads();
#pragma unroll
        for (int k = 0; k < 8; k++) {
            float ra[8], rb[8];
            *(float4*)&ra[0] = *(const float4*)&As[k][ty * 8];
            *(float4*)&ra[4] = *(const float4*)&As[k][ty * 8 + 4];
            *(float4*)&rb[0] = *(const float4*)&Bs[k][tx * 8];
            *(float4*)&rb[4] = *(const float4*)&Bs[k][tx * 8 + 4];
#pragma unroll
            for (int i = 0; i < 8; i++)
#pragma unroll
                for (int j = 0; j < 8; j++)
                    acc[i][j] = fmaf(ra[i], rb[j], acc[i][j]);
        }
        __syncthreads();
    }

    int gc = col0 + tx * 8;
    float4 b0 = make_float4(0.f, 0.f, 0.f, 0.f), b1v = b0;
    if (bias) {
        b0  = *(const float4*)(bias + gc);
        b1v = *(const float4*)(bias + gc + 4);
    }
#pragma unroll
    for (int i = 0; i < 8; i++) {
        int gm = row0 + ty * 8 + i;
        if (gm >= M) continue;
        float4 v0 = make_float4(acc[i][0] + b0.x,  acc[i][1] + b0.y,
                                acc[i][2] + b0.z,  acc[i][3] + b0.w);
        float4 v1 = make_float4(acc[i][4] + b1v.x, acc[i][5] + b1v.y,
                                acc[i][6] + b1v.z, acc[i][7] + b1v.w);
        *(float4*)(C + (size_t)gm * N + gc)     = v0;
        *(float4*)(C + (size_t)gm * N + gc + 4) = v1;
    }
}

// --------------------------- CSR aggregation -------------------------------
// warp per node; lane covers H/32 floats via float4s at cols (lane+32*j)*4.
template <int H>
__global__ void k_agg(const float* __restrict__ xw, const float* __restrict__ bias,
                      float* __restrict__ out) {
    const int NV = H / 128;
    int warp = (blockIdx.x * blockDim.x + threadIdx.x) >> 5;
    int lane = threadIdx.x & 31;
    if (warp >= NN) return;

    float4 acc[NV];
#pragma unroll
    for (int j = 0; j < NV; j++) acc[j] = make_float4(0.f, 0.f, 0.f, 0.f);

    float dvi = g_dinv[warp];
    int e0 = g_off[warp], e1 = g_off[warp + 1];
    for (int e = e0; e < e1; e++) {
        int s = g_csr[e];
        float w = g_dinv[s] * dvi;
        const float4* row = (const float4*)(xw + (size_t)s * H);
#pragma unroll
        for (int j = 0; j < NV; j++) {
            float4 v = __ldg(&row[lane + 32 * j]);
            acc[j].x = fmaf(v.x, w, acc[j].x);
            acc[j].y = fmaf(v.y, w, acc[j].y);
            acc[j].z = fmaf(v.z, w, acc[j].z);
            acc[j].w = fmaf(v.w, w, acc[j].w);
        }
    }
    float4* orow = (float4*)(out + (size_t)warp * H);
    const float4* brow = (const float4*)bias;
#pragma unroll
    for (int j = 0; j < NV; j++) {
        float4 b = brow[lane + 32 * j];
        orow[lane + 32 * j] = make_float4(acc[j].x + b.x, acc[j].y + b.y,
                                          acc[j].z + b.z, acc[j].w + b.w);
    }
}

// --------------------------- BN + PairNorm ---------------------------------
template <int H>
__global__ void k_colstats(const float* __restrict__ h) {
    const int CPT = H / 256;
    int t = threadIdx.x;
    int r0 = blockIdx.x * 256;
    int rend = min(r0 + 256, NN);
    float s[CPT], sq[CPT];
#pragma unroll
    for (int c = 0; c < CPT; c++) { s[c] = 0.f; sq[c] = 0.f; }
    for (int r = r0; r < rend; r++) {
        const float* row = h + (size_t)r * H;
#pragma unroll
        for (int c = 0; c < CPT; c++) {
            float v = row[t + 256 * c];
            s[c] += v; sq[c] += v * v;
        }
    }
#pragma unroll
    for (int c = 0; c < CPT; c++) {
        atomicAdd(&g_colsum[t + 256 * c], s[c]);
        atomicAdd(&g_colsumsq[t + 256 * c], sq[c]);
    }
}

// one block, H threads: fold BN into y = x*a + b; re-zero colsum/colsumsq.
__global__ void k_bnfinal(const float* __restrict__ gamma, const float* __restrict__ beta) {
    int c = threadIdx.x;
    float inv_n = 1.f / (float)NN;
    float mu = g_colsum[c] * inv_n;
    float var = g_colsumsq[c] * inv_n - mu * mu;
    float rs = rsqrtf(var + BN_EPSF);
    float a = rs * gamma[c];
    g_bna[c] = a;
    g_bnb[c] = beta[c] - mu * a;
    g_colsum[c] = 0.f;
    g_colsumsq[c] = 0.f;
}

// apply BN+ReLU in place; accumulate pairnorm column sums and total sum of sq.
template <int H>
__global__ void k_bnapply(float* __restrict__ h) {
    const int CPT = H / 256;
    __shared__ float red[256];
    int t = threadIdx.x;
    int r0 = blockIdx.x * 256;
    int rend = min(r0 + 256, NN);
    float a[CPT], b[CPT], ps[CPT];
    float totsq = 0.f;
#pragma unroll
    for (int c = 0; c < CPT; c++) {
        a[c] = g_bna[t + 256 * c];
        b[c] = g_bnb[t + 256 * c];
        ps[c] = 0.f;
    }
    for (int r = r0; r < rend; r++) {
        float* row = h + (size_t)r * H;
#pragma unroll
        for (int c = 0; c < CPT; c++) {
            float v = row[t + 256 * c];
            float y = fmaxf(fmaf(v, a[c], b[c]), 0.f);
            row[t + 256 * c] = y;
            ps[c] += y;
            totsq = fmaf(y, y, totsq);
        }
    }
#pragma unroll
    for (int c = 0; c < CPT; c++) atomicAdd(&g_pnsum[t + 256 * c], ps[c]);
    red[t] = totsq; __syncthreads();
    for (int o = 128; o > 0; o >>= 1) {
        if (t < o) red[t] += red[t + o];
        __syncthreads();
    }
    if (t == 0) atomicAdd(&g_sumsqtot, red[0]);
}

// one block, 512 threads (H<=512): pnmean, inv denom; re-zero accumulators.
__global__ void k_pnfinal(int H) {
    __shared__ float red[512];
    int c = threadIdx.x;
    float m = 0.f;
    if (c < H) {
        m = g_pnsum[c] / (float)NN;
        g_pnmean[c] = m;
        g_pnsum[c] = 0.f;
    }
    red[c] = m * m; __syncthreads();
    for (int o = 256; o > 0; o >>= 1) {
        if (c < o) red[c] += red[c + o];
        __syncthreads();
    }
    if (c == 0) {
        float msq = red[0];
        float meanrow = (g_sumsqtot - (float)NN * msq) / (float)NN;
        g_invd = 1.f / (sqrtf(fmaxf(meanrow, 0.f)) + PN_EPSF);
        g_sumsqtot = 0.f;
    }
}

// h = (h - pnmean)*invd + xp   (in place), float4 vectorized
template <int H>
__global__ void k_pnapply(float* __restrict__ h, const float* __restrict__ xp) {
    const int TOT4 = NN * H / 4;
    const int W4 = H / 4;
    float invd = g_invd;
    const float4* pm = (const float4*)g_pnmean;
    const float4* xp4 = (const float4*)xp;
    float4* h4 = (float4*)h;
    for (int i = blockIdx.x * blockDim.x + threadIdx.x; i < TOT4;
         i += gridDim.x * blockDim.x) {
        float4 m = pm[i % W4];
        float4 v = h4[i];
        float4 r = xp4[i];
        v.x = fmaf(v.x - m.x, invd, r.x);
        v.y = fmaf(v.y - m.y, invd, r.y);
        v.z = fmaf(v.z - m.z, invd, r.z);
        v.w = fmaf(v.w - m.w, invd, r.w);
        h4[i] = v;
    }
}

// ------------------------------ launcher -----------------------------------
extern "C" void kernel_launch(void* const* d_in, const int* in_sizes, int n_in,
                              void* d_out, int out_size) {
    const float* x   = (const float*)d_in[0];
    const int*   ei  = (const int*)  d_in[1];
    const float* W1  = (const float*)d_in[2];
    const float* b1  = (const float*)d_in[3];
    const float* ga1 = (const float*)d_in[4];
    const float* be1 = (const float*)d_in[5];
    const float* W2  = (const float*)d_in[6];
    const float* b2  = (const float*)d_in[7];
    const float* ga2 = (const float*)d_in[8];
    const float* be2 = (const float*)d_in[9];
    const float* P1w = (const float*)d_in[10];
    const float* P1b = (const float*)d_in[11];
    const float* P2w = (const float*)d_in[12];
    const float* P2b = (const float*)d_in[13];
    float* out = (float*)d_out;

    float *xw, *xp, *h;
    cudaGetSymbolAddress((void**)&xw, g_xw);
    cudaGetSymbolAddress((void**)&xp, g_xp);
    cudaGetSymbolAddress((void**)&h,  g_h);

    const int* esrc = ei;
    const int* edst = ei + EE;

    // ---- graph prep (CSR by dst, incl. self loops) ----
    k_init <<<(NN + 255) / 256, 256>>>();
    k_count<<<(EE + 255) / 256, 256>>>(edst);
    k_dinv <<<(NN + 255) / 256, 256>>>();
    k_scan1<<<SCAN_NB, SCAN_CH>>>();
    k_scan2<<<1, 1024>>>();
    k_scan3<<<SCAN_NB, SCAN_CH>>>();
    k_fill <<<(TOTE + 255) / 256, 256>>>(esrc, edst);

    // ---- layer 1 ----
    dim3 gg1(H1D / 128, (NN + 127) / 128);
    k_sgemm<<<gg1, 256>>>(x, W1,  nullptr, xw, NN, H1D, IND);
    k_sgemm<<<gg1, 256>>>(x, P1w, P1b,     xp, NN, H1D, IND);
    k_agg<H1D><<<(NN + 7) / 8, 256>>>(xw, b1, h);
    k_colstats<H1D><<<(NN + 255) / 256, 256>>>(h);
    k_bnfinal<<<1, H1D>>>(ga1, be1);
    k_bnapply<H1D><<<(NN + 255) / 256, 256>>>(h);
    k_pnfinal<<<1, 512>>>(H1D);
    k_pnapply<H1D><<<2048, 256>>>(h, xp);

    // ---- layer 2 ----
    dim3 gg2(H2D / 128, (NN + 127) / 128);
    k_sgemm<<<gg2, 256>>>(h, W2,  nullptr, xw, NN, H2D, H1D);
    k_sgemm<<<gg2, 256>>>(h, P2w, P2b,     xp, NN, H2D, H1D);
    k_agg<H2D><<<(NN + 7) / 8, 256>>>(xw, b2, out);
    k_colstats<H2D><<<(NN + 255) / 256, 256>>>(out);
    k_bnfinal<<<1, H2D>>>(ga2, be2);
    k_bnapply<H2D><<<(NN + 255) / 256, 256>>>(out);
    k_pnfinal<<<1, 512>>>(H2D);
    k_pnapply<H2D><<<2048, 256>>>(out, xp);
}

// round 4
// speedup vs baseline: 2.0854x; 2.0854x over previous
#include <cuda_runtime.h>
#include <cuda_bf16.h>
#include <cstdint>

// ---------------------------------------------------------------------------
// BetterGCN: 2-layer GCN (GCNConv -> BN -> ReLU -> PairNorm -> +residual proj)
// GEMMs: bf16 hi/lo split (3-product) on mma.sync tensor cores (sm_100 legal).
// ---------------------------------------------------------------------------
#define NN    50000
#define EE    800000
#define TOTE  (EE + NN)
#define IND   500
#define KP    512
#define H1D   512
#define H2D   256
#define BN_EPSF 1e-5f
#define PN_EPSF 1e-12f

#define SCAN_CH 64
#define SCAN_NB ((NN + SCAN_CH - 1) / SCAN_CH)

typedef __nv_bfloat16 bf16;

// ------------------------- device scratch (no allocs) ----------------------
__device__ float g_xw[(size_t)NN * H1D];
__device__ float g_xp[(size_t)NN * H1D];
__device__ float g_h [(size_t)NN * H1D];

__device__ bf16 g_xh[(size_t)NN * KP];
__device__ bf16 g_xl[(size_t)NN * KP];
__device__ bf16 g_hh[(size_t)NN * KP];
__device__ bf16 g_hl[(size_t)NN * KP];

__device__ bf16 g_w1h[(size_t)H1D * KP], g_w1l[(size_t)H1D * KP];
__device__ bf16 g_p1h[(size_t)H1D * KP], g_p1l[(size_t)H1D * KP];
__device__ bf16 g_w2h[(size_t)H2D * KP], g_w2l[(size_t)H2D * KP];
__device__ bf16 g_p2h[(size_t)H2D * KP], g_p2l[(size_t)H2D * KP];

__device__ int   g_cnt[NN];
__device__ float g_dinv[NN];
__device__ int   g_off[NN + 1];
__device__ int   g_cur[NN];
__device__ int   g_csr[TOTE];
__device__ int   g_part[1024];

__device__ float g_colsum[H1D], g_colsumsq[H1D];
__device__ float g_bna[H1D], g_bnb[H1D];
__device__ float g_pnsum[H1D], g_pnmean[H1D];
__device__ float g_sumsqtot;
__device__ float g_invd;

// --------------------------- PTX helpers (sm_100-legal) --------------------
__device__ __forceinline__ uint32_t smem_u32(const void* p) {
    uint32_t a;
    asm("{ .reg .u64 t; cvta.to.shared.u64 t, %1; cvt.u32.u64 %0, t; }"
        : "=r"(a) : "l"(p));
    return a;
}
__device__ __forceinline__ void cpa16(uint32_t dst, const void* src, int szok) {
    asm volatile("cp.async.cg.shared.global [%0], [%1], 16, %2;"
                 :: "r"(dst), "l"(src), "r"(szok) : "memory");
}
__device__ __forceinline__ void cpa_commit() {
    asm volatile("cp.async.commit_group;" ::: "memory");
}
__device__ __forceinline__ void cpa_wait2() {
    asm volatile("cp.async.wait_group 2;" ::: "memory");
}
__device__ __forceinline__ void ldsm4(uint32_t* r, uint32_t a) {
    asm volatile("ldmatrix.sync.aligned.m8n8.x4.shared.b16 {%0,%1,%2,%3}, [%4];"
                 : "=r"(r[0]), "=r"(r[1]), "=r"(r[2]), "=r"(r[3]) : "r"(a));
}
__device__ __forceinline__ void mma16816(float* c, const uint32_t* a, const uint32_t* b) {
    asm volatile(
        "mma.sync.aligned.m16n8k16.row.col.f32.bf16.bf16.f32 "
        "{%0,%1,%2,%3}, {%4,%5,%6,%7}, {%8,%9}, {%0,%1,%2,%3};"
        : "+f"(c[0]), "+f"(c[1]), "+f"(c[2]), "+f"(c[3])
        : "r"(a[0]), "r"(a[1]), "r"(a[2]), "r"(a[3]), "r"(b[0]), "r"(b[1]));
}
#define SWZ(o) ((o) ^ (((o) >> 3) & 0x70))

// ------------------------------- CSR build ---------------------------------
__global__ void k_init() {
    int i = blockIdx.x * blockDim.x + threadIdx.x;
    if (i < NN) g_cnt[i] = 1;
    if (i < H1D) { g_colsum[i] = 0.f; g_colsumsq[i] = 0.f; g_pnsum[i] = 0.f; }
    if (i == 0) g_sumsqtot = 0.f;
}
__global__ void k_count(const int* __restrict__ dst) {
    int e = blockIdx.x * blockDim.x + threadIdx.x;
    if (e < EE) atomicAdd(&g_cnt[dst[e]], 1);
}
__global__ void k_dinv() {
    int i = blockIdx.x * blockDim.x + threadIdx.x;
    if (i < NN) g_dinv[i] = rsqrtf((float)g_cnt[i]);
}
__global__ void k_scan1() {
    __shared__ int s[SCAN_CH];
    int b = blockIdx.x, t = threadIdx.x;
    int i = b * SCAN_CH + t;
    int v = (i < NN) ? g_cnt[i] : 0;
    s[t] = v; __syncthreads();
    for (int o = 1; o < SCAN_CH; o <<= 1) {
        int u = (t >= o) ? s[t - o] : 0;
        __syncthreads(); s[t] += u; __syncthreads();
    }
    if (i < NN) g_off[i] = s[t] - v;
    if (t == SCAN_CH - 1) g_part[b] = s[t];
}
__global__ void k_scan2() {
    __shared__ int s[1024];
    int t = threadIdx.x;
    int v = (t < SCAN_NB) ? g_part[t] : 0;
    s[t] = v; __syncthreads();
    for (int o = 1; o < 1024; o <<= 1) {
        int u = (t >= o) ? s[t - o] : 0;
        __syncthreads(); s[t] += u; __syncthreads();
    }
    if (t < SCAN_NB) g_part[t] = s[t] - v;
    if (t == SCAN_NB - 1) g_off[NN] = s[t];
}
__global__ void k_scan3() {
    int b = blockIdx.x, t = threadIdx.x;
    int i = b * SCAN_CH + t;
    if (i < NN) { int o = g_off[i] + g_part[b]; g_off[i] = o; g_cur[i] = o; }
}
__global__ void k_fill(const int* __restrict__ src, const int* __restrict__ dst) {
    int t = blockIdx.x * blockDim.x + threadIdx.x;
    if (t >= TOTE) return;
    int s, d;
    if (t < EE) { s = src[t]; d = dst[t]; }
    else        { s = t - EE; d = s; }
    g_csr[atomicAdd(&g_cur[d], 1)] = s;
}

// ------------------------- bf16 split conversions ---------------------------
__global__ void k_splitx(const float* __restrict__ x) {
    size_t i = (size_t)blockIdx.x * blockDim.x + threadIdx.x;
    if (i >= (size_t)NN * KP) return;
    int k = (int)(i & (KP - 1));
    size_t r = i >> 9;
    float v = (k < IND) ? x[r * IND + k] : 0.f;
    bf16 hi = __float2bfloat16(v);
    bf16 lo = __float2bfloat16(v - __bfloat162float(hi));
    g_xh[i] = hi; g_xl[i] = lo;
}
__global__ void k_splitw(const float* __restrict__ W, bf16* __restrict__ oh,
                         bf16* __restrict__ ol, int Kv, int Nt) {
    size_t i = (size_t)blockIdx.x * blockDim.x + threadIdx.x;
    if (i >= (size_t)Nt * KP) return;
    int k = (int)(i & (KP - 1));
    int n = (int)(i >> 9);
    float v = (k < Kv) ? W[(size_t)k * Nt + n] : 0.f;
    bf16 hi = __float2bfloat16(v);
    bf16 lo = __float2bfloat16(v - __bfloat162float(hi));
    oh[i] = hi; ol[i] = lo;
}

// --------------------- mma.sync split-bf16 GEMM ----------------------------
// C[M,Ntot] = (Ah+Al) @ (Bh+Bl)^T + bias, A [M,512], B [Ntot,512] (K-major).
// CTA 128x128, BK=64, 3-stage cp.async pipeline, 8 warps (2x4), warp 64x32.
#define NSTAGE 3
#define STG 65536                 // Ah 16K | Al 16K | Bh 16K | Bl 16K
#define GEMM_SMEM (NSTAGE * STG)

__global__ __launch_bounds__(256)
void k_gemm_mma(const bf16* __restrict__ Ah, const bf16* __restrict__ Al,
                const bf16* __restrict__ Bh, const bf16* __restrict__ Bl,
                const float* __restrict__ bias, float* __restrict__ C,
                int M, int Ntot) {
    extern __shared__ char sm[];
    uint32_t sbase = smem_u32(sm);
    int tid = threadIdx.x, lane = tid & 31, wid = tid >> 5;
    int warp_m = wid >> 2, warp_n = wid & 3;
    int row0 = blockIdx.y * 128, col0 = blockIdx.x * 128;

    float acc[4][4][4];
#pragma unroll
    for (int i = 0; i < 4; i++)
#pragma unroll
        for (int j = 0; j < 4; j++)
#pragma unroll
            for (int v = 0; v < 4; v++) acc[i][j][v] = 0.f;

    const int NK = 8;   // 512 / 64 stages of K

    auto load_stage = [&](int s) {
        uint32_t sb = sbase + (s % NSTAGE) * STG;
        int k0 = s * 64;
#pragma unroll
        for (int i = 0; i < 4; i++) {
            int idx = tid + i * 256;          // 1024 chunks of 16B
            int r = idx >> 3, seg = idx & 7;
            int gr = row0 + r;
            int ok = (gr < M) ? 16 : 0;
            size_t off = (size_t)(gr < M ? gr : 0) * KP + k0 + seg * 8;
            uint32_t so = SWZ((uint32_t)(r * 128 + seg * 16));
            cpa16(sb + so,         Ah + off, ok);
            cpa16(sb + 16384 + so, Al + off, ok);
            size_t boff = (size_t)(col0 + r) * KP + k0 + seg * 8;
            cpa16(sb + 32768 + so, Bh + boff, 16);
            cpa16(sb + 49152 + so, Bl + boff, 16);
        }
    };

    load_stage(0); cpa_commit();
    load_stage(1); cpa_commit();

    for (int s = 0; s < NK; s++) {
        if (s + 2 < NK) load_stage(s + 2);
        cpa_commit();
        cpa_wait2();
        __syncthreads();

        uint32_t sb = sbase + (s % NSTAGE) * STG;
#pragma unroll
        for (int ks = 0; ks < 4; ks++) {
            uint32_t ah[4][4], al[4][4], bh[2][4], bl[2][4];
#pragma unroll
            for (int mt = 0; mt < 4; mt++) {
                int row = warp_m * 64 + mt * 16 + (lane & 15);
                int cb = ks * 32 + (lane >> 4) * 16;     // byte offset in 128B row
                uint32_t ad = sb + SWZ((uint32_t)(row * 128 + cb));
                ldsm4(ah[mt], ad);
                ldsm4(al[mt], ad + 16384);
            }
#pragma unroll
            for (int bt = 0; bt < 2; bt++) {
                int g = lane >> 3, r = lane & 7;
                int n = warp_n * 32 + bt * 16 + (g >> 1) * 8 + r;
                int kb = ks * 32 + (g & 1) * 16;
                uint32_t bd = sb + 32768 + SWZ((uint32_t)(n * 128 + kb));
                ldsm4(bh[bt], bd);
                ldsm4(bl[bt], bd + 16384);
            }
#pragma unroll
            for (int mt = 0; mt < 4; mt++)
#pragma unroll
                for (int bt = 0; bt < 2; bt++) {
                    mma16816(acc[mt][bt * 2],     ah[mt], &bh[bt][0]);
                    mma16816(acc[mt][bt * 2],     ah[mt], &bl[bt][0]);
                    mma16816(acc[mt][bt * 2],     al[mt], &bh[bt][0]);
                    mma16816(acc[mt][bt * 2 + 1], ah[mt], &bh[bt][2]);
                    mma16816(acc[mt][bt * 2 + 1], ah[mt], &bl[bt][2]);
                    mma16816(acc[mt][bt * 2 + 1], al[mt], &bh[bt][2]);
                }
        }
        __syncthreads();
    }

    // ---- epilogue ----
#pragma unroll
    for (int mt = 0; mt < 4; mt++)
#pragma unroll
        for (int nt = 0; nt < 4; nt++) {
            int r = row0 + warp_m * 64 + mt * 16 + (lane >> 2);
            int c = col0 + warp_n * 32 + nt * 8 + (lane & 3) * 2;
            float b0 = bias ? __ldg(&bias[c]) : 0.f;
            float b1 = bias ? __ldg(&bias[c + 1]) : 0.f;
            if (r < M) {
                float2* p = (float2*)(C + (size_t)r * Ntot + c);
                *p = make_float2(acc[mt][nt][0] + b0, acc[mt][nt][1] + b1);
            }
            if (r + 8 < M) {
                float2* p = (float2*)(C + (size_t)(r + 8) * Ntot + c);
                *p = make_float2(acc[mt][nt][2] + b0, acc[mt][nt][3] + b1);
            }
        }
}

// --------------------------- CSR aggregation -------------------------------
template <int H>
__global__ void k_agg(const float* __restrict__ xw, const float* __restrict__ bias,
                      float* __restrict__ out) {
    const int NV = H / 128;
    int warp = (blockIdx.x * blockDim.x + threadIdx.x) >> 5;
    int lane = threadIdx.x & 31;
    if (warp >= NN) return;
    float4 acc[NV];
#pragma unroll
    for (int j = 0; j < NV; j++) acc[j] = make_float4(0.f, 0.f, 0.f, 0.f);
    float dvi = g_dinv[warp];
    int e0 = g_off[warp], e1 = g_off[warp + 1];
    for (int e = e0; e < e1; e++) {
        int s = g_csr[e];
        float w = g_dinv[s] * dvi;
        const float4* row = (const float4*)(xw + (size_t)s * H);
#pragma unroll
        for (int j = 0; j < NV; j++) {
            float4 v = __ldg(&row[lane + 32 * j]);
            acc[j].x = fmaf(v.x, w, acc[j].x);
            acc[j].y = fmaf(v.y, w, acc[j].y);
            acc[j].z = fmaf(v.z, w, acc[j].z);
            acc[j].w = fmaf(v.w, w, acc[j].w);
        }
    }
    float4* orow = (float4*)(out + (size_t)warp * H);
    const float4* brow = (const float4*)bias;
#pragma unroll
    for (int j = 0; j < NV; j++) {
        float4 b = brow[lane + 32 * j];
        orow[lane + 32 * j] = make_float4(acc[j].x + b.x, acc[j].y + b.y,
                                          acc[j].z + b.z, acc[j].w + b.w);
    }
}

// --------------------------- BN + PairNorm ---------------------------------
template <int H>
__global__ void k_colstats(const float* __restrict__ h) {
    const int CPT = H / 256;
    int t = threadIdx.x;
    int r0 = blockIdx.x * 256;
    int rend = min(r0 + 256, NN);
    float s[CPT], sq[CPT];
#pragma unroll
    for (int c = 0; c < CPT; c++) { s[c] = 0.f; sq[c] = 0.f; }
    for (int r = r0; r < rend; r++) {
        const float* row = h + (size_t)r * H;
#pragma unroll
        for (int c = 0; c < CPT; c++) {
            float v = row[t + 256 * c];
            s[c] += v; sq[c] += v * v;
        }
    }
#pragma unroll
    for (int c = 0; c < CPT; c++) {
        atomicAdd(&g_colsum[t + 256 * c], s[c]);
        atomicAdd(&g_colsumsq[t + 256 * c], sq[c]);
    }
}
__global__ void k_bnfinal(const float* __restrict__ gamma, const float* __restrict__ beta) {
    int c = threadIdx.x;
    float inv_n = 1.f / (float)NN;
    float mu = g_colsum[c] * inv_n;
    float var = g_colsumsq[c] * inv_n - mu * mu;
    float a = rsqrtf(var + BN_EPSF) * gamma[c];
    g_bna[c] = a;
    g_bnb[c] = beta[c] - mu * a;
    g_colsum[c] = 0.f; g_colsumsq[c] = 0.f;
}
template <int H>
__global__ void k_bnapply(float* __restrict__ h) {
    const int CPT = H / 256;
    __shared__ float red[256];
    int t = threadIdx.x;
    int r0 = blockIdx.x * 256;
    int rend = min(r0 + 256, NN);
    float a[CPT], b[CPT], ps[CPT];
    float totsq = 0.f;
#pragma unroll
    for (int c = 0; c < CPT; c++) {
        a[c] = g_bna[t + 256 * c]; b[c] = g_bnb[t + 256 * c]; ps[c] = 0.f;
    }
    for (int r = r0; r < rend; r++) {
        float* row = h + (size_t)r * H;
#pragma unroll
        for (int c = 0; c < CPT; c++) {
            float v = row[t + 256 * c];
            float y = fmaxf(fmaf(v, a[c], b[c]), 0.f);
            row[t + 256 * c] = y;
            ps[c] += y;
            totsq = fmaf(y, y, totsq);
        }
    }
#pragma unroll
    for (int c = 0; c < CPT; c++) atomicAdd(&g_pnsum[t + 256 * c], ps[c]);
    red[t] = totsq; __syncthreads();
    for (int o = 128; o > 0; o >>= 1) {
        if (t < o) red[t] += red[t + o];
        __syncthreads();
    }
    if (t == 0) atomicAdd(&g_sumsqtot, red[0]);
}
__global__ void k_pnfinal(int H) {
    __shared__ float red[512];
    int c = threadIdx.x;
    float m = 0.f;
    if (c < H) { m = g_pnsum[c] / (float)NN; g_pnmean[c] = m; g_pnsum[c] = 0.f; }
    red[c] = m * m; __syncthreads();
    for (int o = 256; o > 0; o >>= 1) {
        if (c < o) red[c] += red[c + o];
        __syncthreads();
    }
    if (c == 0) {
        float meanrow = (g_sumsqtot - (float)NN * red[0]) / (float)NN;
        g_invd = 1.f / (sqrtf(fmaxf(meanrow, 0.f)) + PN_EPSF);
        g_sumsqtot = 0.f;
    }
}
template <int H>
__global__ void k_pnapply(float* __restrict__ h, const float* __restrict__ xp) {
    const int TOT4 = NN * H / 4;
    const int W4 = H / 4;
    float invd = g_invd;
    const float4* pm = (const float4*)g_pnmean;
    const float4* xp4 = (const float4*)xp;
    float4* h4 = (float4*)h;
    for (int i = blockIdx.x * blockDim.x + threadIdx.x; i < TOT4;
         i += gridDim.x * blockDim.x) {
        float4 m = pm[i % W4];
        float4 v = h4[i];
        float4 r = xp4[i];
        v.x = fmaf(v.x - m.x, invd, r.x);
        v.y = fmaf(v.y - m.y, invd, r.y);
        v.z = fmaf(v.z - m.z, invd, r.z);
        v.w = fmaf(v.w - m.w, invd, r.w);
        h4[i] = v;
    }
}
// layer-1 final: h1 -> bf16 hi/lo split directly (feeds layer-2 GEMMs)
__global__ void k_pnapply_split(const float* __restrict__ h, const float* __restrict__ xp) {
    float invd = g_invd;
    for (size_t i = (size_t)blockIdx.x * blockDim.x + threadIdx.x;
         i < (size_t)NN * H1D; i += (size_t)gridDim.x * blockDim.x) {
        int c = (int)(i & (H1D - 1));
        float v = fmaf(h[i] - g_pnmean[c], invd, xp[i]);
        bf16 hi = __float2bfloat16(v);
        bf16 lo = __float2bfloat16(v - __bfloat162float(hi));
        g_hh[i] = hi; g_hl[i] = lo;
    }
}

// ------------------------------ launcher -----------------------------------
extern "C" void kernel_launch(void* const* d_in, const int* in_sizes, int n_in,
                              void* d_out, int out_size) {
    const float* x   = (const float*)d_in[0];
    const int*   ei  = (const int*)  d_in[1];
    const float* W1  = (const float*)d_in[2];
    const float* b1  = (const float*)d_in[3];
    const float* ga1 = (const float*)d_in[4];
    const float* be1 = (const float*)d_in[5];
    const float* W2  = (const float*)d_in[6];
    const float* b2  = (const float*)d_in[7];
    const float* ga2 = (const float*)d_in[8];
    const float* be2 = (const float*)d_in[9];
    const float* P1w = (const float*)d_in[10];
    const float* P1b = (const float*)d_in[11];
    const float* P2w = (const float*)d_in[12];
    const float* P2b = (const float*)d_in[13];
    float* out = (float*)d_out;

    // idempotent, deterministic — no static guard (harness rule)
    cudaFuncSetAttribute(k_gemm_mma, cudaFuncAttributeMaxDynamicSharedMemorySize,
                         GEMM_SMEM);

    float *xw, *xp, *h;
    cudaGetSymbolAddress((void**)&xw, g_xw);
    cudaGetSymbolAddress((void**)&xp, g_xp);
    cudaGetSymbolAddress((void**)&h,  g_h);
    bf16 *xh, *xl, *hh, *hl, *w1h, *w1l, *p1h, *p1l, *w2h, *w2l, *p2h, *p2l;
    cudaGetSymbolAddress((void**)&xh, g_xh);   cudaGetSymbolAddress((void**)&xl, g_xl);
    cudaGetSymbolAddress((void**)&hh, g_hh);   cudaGetSymbolAddress((void**)&hl, g_hl);
    cudaGetSymbolAddress((void**)&w1h, g_w1h); cudaGetSymbolAddress((void**)&w1l, g_w1l);
    cudaGetSymbolAddress((void**)&p1h, g_p1h); cudaGetSymbolAddress((void**)&p1l, g_p1l);
    cudaGetSymbolAddress((void**)&w2h, g_w2h); cudaGetSymbolAddress((void**)&w2l, g_w2l);
    cudaGetSymbolAddress((void**)&p2h, g_p2h); cudaGetSymbolAddress((void**)&p2l, g_p2l);

    const int* esrc = ei;
    const int* edst = ei + EE;

    // ---- graph prep + conversions ----
    k_init <<<(NN + 255) / 256, 256>>>();
    k_count<<<(EE + 255) / 256, 256>>>(edst);
    k_dinv <<<(NN + 255) / 256, 256>>>();
    k_scan1<<<SCAN_NB, SCAN_CH>>>();
    k_scan2<<<1, 1024>>>();
    k_scan3<<<SCAN_NB, SCAN_CH>>>();
    k_fill <<<(TOTE + 255) / 256, 256>>>(esrc, edst);

    k_splitx<<<(int)(((size_t)NN * KP + 255) / 256), 256>>>(x);
    k_splitw<<<(H1D * KP + 255) / 256, 256>>>(W1,  w1h, w1l, IND, H1D);
    k_splitw<<<(H1D * KP + 255) / 256, 256>>>(P1w, p1h, p1l, IND, H1D);
    k_splitw<<<(H2D * KP + 255) / 256, 256>>>(W2,  w2h, w2l, H1D, H2D);
    k_splitw<<<(H2D * KP + 255) / 256, 256>>>(P2w, p2h, p2l, H1D, H2D);

    const int MROWS = (NN + 127) / 128;   // 391

    // ---- layer 1 ----
    k_gemm_mma<<<dim3(H1D / 128, MROWS), 256, GEMM_SMEM>>>(xh, xl, w1h, w1l, nullptr, xw, NN, H1D);
    k_gemm_mma<<<dim3(H1D / 128, MROWS), 256, GEMM_SMEM>>>(xh, xl, p1h, p1l, P1b, xp, NN, H1D);
    k_agg<H1D><<<(NN + 7) / 8, 256>>>(xw, b1, h);
    k_colstats<H1D><<<(NN + 255) / 256, 256>>>(h);
    k_bnfinal<<<1, H1D>>>(ga1, be1);
    k_bnapply<H1D><<<(NN + 255) / 256, 256>>>(h);
    k_pnfinal<<<1, 512>>>(H1D);
    k_pnapply_split<<<2048, 256>>>(h, xp);

    // ---- layer 2 ----
    k_gemm_mma<<<dim3(H2D / 128, MROWS), 256, GEMM_SMEM>>>(hh, hl, w2h, w2l, nullptr, xw, NN, H2D);
    k_gemm_mma<<<dim3(H2D / 128, MROWS), 256, GEMM_SMEM>>>(hh, hl, p2h, p2l, P2b, xp, NN, H2D);
    k_agg<H2D><<<(NN + 7) / 8, 256>>>(xw, b2, out);
    k_colstats<H2D><<<(NN + 255) / 256, 256>>>(out);
    k_bnfinal<<<1, H2D>>>(ga2, be2);
    k_bnapply<H2D><<<(NN + 255) / 256, 256>>>(out);
    k_pnfinal<<<1, 512>>>(H2D);
    k_pnapply<H2D><<<2048, 256>>>(out, xp);
}

// round 6
// speedup vs baseline: 2.0963x; 1.0052x over previous
#include <cuda_runtime.h>
#include <cuda_bf16.h>
#include <cstdint>

// ---------------------------------------------------------------------------
// BetterGCN: 2-layer GCN (GCNConv -> BN -> ReLU -> PairNorm -> +residual proj)
// GEMMs: bf16 hi/lo split (3-product) on mma.sync tensor cores (sm_100 legal).
// ---------------------------------------------------------------------------
#define NN    50000
#define EE    800000
#define TOTE  (EE + NN)
#define IND   500
#define KP    512
#define H1D   512
#define H2D   256
#define BN_EPSF 1e-5f
#define PN_EPSF 1e-12f

#define SCAN_CH 64
#define SCAN_NB ((NN + SCAN_CH - 1) / SCAN_CH)

typedef __nv_bfloat16 bf16;

// ------------------------- device scratch (no allocs) ----------------------
__device__ float g_xw[(size_t)NN * H1D];
__device__ float g_xp[(size_t)NN * H1D];
__device__ float g_h [(size_t)NN * H1D];

__device__ bf16 g_xh[(size_t)NN * KP];
__device__ bf16 g_xl[(size_t)NN * KP];
__device__ bf16 g_hh[(size_t)NN * KP];
__device__ bf16 g_hl[(size_t)NN * KP];

__device__ bf16 g_w1h[(size_t)H1D * KP], g_w1l[(size_t)H1D * KP];
__device__ bf16 g_p1h[(size_t)H1D * KP], g_p1l[(size_t)H1D * KP];
__device__ bf16 g_w2h[(size_t)H2D * KP], g_w2l[(size_t)H2D * KP];
__device__ bf16 g_p2h[(size_t)H2D * KP], g_p2l[(size_t)H2D * KP];

__device__ int   g_cnt[NN];
__device__ float g_dinv[NN];
__device__ int   g_off[NN + 1];
__device__ int   g_cur[NN];
__device__ int   g_csr[TOTE];
__device__ int   g_part[1024];

__device__ float g_colsum[H1D], g_colsumsq[H1D];
__device__ float g_bna[H1D], g_bnb[H1D];
__device__ float g_pnsum[H1D], g_pnmean[H1D];
__device__ float g_sumsqtot;
__device__ float g_invd;

// --------------------------- PTX helpers (sm_100-legal) --------------------
__device__ __forceinline__ uint32_t smem_u32(const void* p) {
    uint32_t a;
    asm("{ .reg .u64 t; cvta.to.shared.u64 t, %1; cvt.u32.u64 %0, t; }"
        : "=r"(a) : "l"(p));
    return a;
}
__device__ __forceinline__ void cpa16(uint32_t dst, const void* src, int szok) {
    asm volatile("cp.async.cg.shared.global [%0], [%1], 16, %2;"
                 :: "r"(dst), "l"(src), "r"(szok) : "memory");
}
__device__ __forceinline__ void cpa_commit() {
    asm volatile("cp.async.commit_group;" ::: "memory");
}
__device__ __forceinline__ void cpa_wait2() {
    asm volatile("cp.async.wait_group 2;" ::: "memory");
}
__device__ __forceinline__ void ldsm4(uint32_t* r, uint32_t a) {
    asm volatile("ldmatrix.sync.aligned.m8n8.x4.shared.b16 {%0,%1,%2,%3}, [%4];"
                 : "=r"(r[0]), "=r"(r[1]), "=r"(r[2]), "=r"(r[3]) : "r"(a));
}
__device__ __forceinline__ void mma16816(float* c, const uint32_t* a, const uint32_t* b) {
    asm volatile(
        "mma.sync.aligned.m16n8k16.row.col.f32.bf16.bf16.f32 "
        "{%0,%1,%2,%3}, {%4,%5,%6,%7}, {%8,%9}, {%0,%1,%2,%3};"
        : "+f"(c[0]), "+f"(c[1]), "+f"(c[2]), "+f"(c[3])
        : "r"(a[0]), "r"(a[1]), "r"(a[2]), "r"(a[3]), "r"(b[0]), "r"(b[1]));
}
#define SWZ(o) ((o) ^ (((o) >> 3) & 0x70))

// ------------------------------- CSR build ---------------------------------
__global__ void k_init() {
    int i = blockIdx.x * blockDim.x + threadIdx.x;
    if (i < NN) g_cnt[i] = 1;
    if (i < H1D) { g_colsum[i] = 0.f; g_colsumsq[i] = 0.f; g_pnsum[i] = 0.f; }
    if (i == 0) g_sumsqtot = 0.f;
}
__global__ void k_count(const int* __restrict__ dst) {
    int e = blockIdx.x * blockDim.x + threadIdx.x;
    if (e < EE) atomicAdd(&g_cnt[dst[e]], 1);
}
__global__ void k_dinv() {
    int i = blockIdx.x * blockDim.x + threadIdx.x;
    if (i < NN) g_dinv[i] = rsqrtf((float)g_cnt[i]);
}
__global__ void k_scan1() {
    __shared__ int s[SCAN_CH];
    int b = blockIdx.x, t = threadIdx.x;
    int i = b * SCAN_CH + t;
    int v = (i < NN) ? g_cnt[i] : 0;
    s[t] = v; __syncthreads();
    for (int o = 1; o < SCAN_CH; o <<= 1) {
        int u = (t >= o) ? s[t - o] : 0;
        __syncthreads(); s[t] += u; __syncthreads();
    }
    if (i < NN) g_off[i] = s[t] - v;
    if (t == SCAN_CH - 1) g_part[b] = s[t];
}
__global__ void k_scan2() {
    __shared__ int s[1024];
    int t = threadIdx.x;
    int v = (t < SCAN_NB) ? g_part[t] : 0;
    s[t] = v; __syncthreads();
    for (int o = 1; o < 1024; o <<= 1) {
        int u = (t >= o) ? s[t - o] : 0;
        __syncthreads(); s[t] += u; __syncthreads();
    }
    if (t < SCAN_NB) g_part[t] = s[t] - v;
    if (t == SCAN_NB - 1) g_off[NN] = s[t];
}
__global__ void k_scan3() {
    int b = blockIdx.x, t = threadIdx.x;
    int i = b * SCAN_CH + t;
    if (i < NN) { int o = g_off[i] + g_part[b]; g_off[i] = o; g_cur[i] = o; }
}
__global__ void k_fill(const int* __restrict__ src, const int* __restrict__ dst) {
    int t = blockIdx.x * blockDim.x + threadIdx.x;
    if (t >= TOTE) return;
    int s, d;
    if (t < EE) { s = src[t]; d = dst[t]; }
    else        { s = t - EE; d = s; }
    g_csr[atomicAdd(&g_cur[d], 1)] = s;
}

// ------------------------- bf16 split conversions ---------------------------
__global__ void k_splitx(const float* __restrict__ x) {
    size_t i = (size_t)blockIdx.x * blockDim.x + threadIdx.x;
    if (i >= (size_t)NN * KP) return;
    int k = (int)(i & (KP - 1));
    size_t r = i >> 9;
    float v = (k < IND) ? x[r * IND + k] : 0.f;
    bf16 hi = __float2bfloat16(v);
    bf16 lo = __float2bfloat16(v - __bfloat162float(hi));
    g_xh[i] = hi; g_xl[i] = lo;
}
__global__ void k_splitw(const float* __restrict__ W, bf16* __restrict__ oh,
                         bf16* __restrict__ ol, int Kv, int Nt) {
    size_t i = (size_t)blockIdx.x * blockDim.x + threadIdx.x;
    if (i >= (size_t)Nt * KP) return;
    int k = (int)(i & (KP - 1));
    int n = (int)(i >> 9);
    float v = (k < Kv) ? W[(size_t)k * Nt + n] : 0.f;
    bf16 hi = __float2bfloat16(v);
    bf16 lo = __float2bfloat16(v - __bfloat162float(hi));
    oh[i] = hi; ol[i] = lo;
}

// --------------------- mma.sync split-bf16 GEMM ----------------------------
// Fused per-layer: grid.x = 2 * (H/128). First half computes A@Bw^T -> Cw,
// second half A@Bp^T (+bias) -> Cp. CTA 128x128, BK=64, 3-stage cp.async.
#define NSTAGE 3
#define STG 65536                 // Ah 16K | Al 16K | Bh 16K | Bl 16K
#define GEMM_SMEM (NSTAGE * STG)

__global__ __launch_bounds__(256)
void k_gemm_mma(const bf16* __restrict__ Ah, const bf16* __restrict__ Al,
                const bf16* __restrict__ Bwh, const bf16* __restrict__ Bwl,
                const bf16* __restrict__ Bph, const bf16* __restrict__ Bpl,
                const float* __restrict__ biasP,
                float* __restrict__ Cw, float* __restrict__ Cp,
                int M, int Ntot) {
    extern __shared__ char sm[];
    uint32_t sbase = smem_u32(sm);
    int tid = threadIdx.x, lane = tid & 31, wid = tid >> 5;
    int warp_m = wid >> 2, warp_n = wid & 3;
    int nb = Ntot >> 7;                       // col blocks per matrix
    int isP = blockIdx.x >= nb;
    int cblk = isP ? (blockIdx.x - nb) : blockIdx.x;
    const bf16* Bh = isP ? Bph : Bwh;
    const bf16* Bl = isP ? Bpl : Bwl;
    const float* bias = isP ? biasP : nullptr;
    float* C = isP ? Cp : Cw;
    int row0 = blockIdx.y * 128, col0 = cblk * 128;

    float acc[4][4][4];
#pragma unroll
    for (int i = 0; i < 4; i++)
#pragma unroll
        for (int j = 0; j < 4; j++)
#pragma unroll
            for (int v = 0; v < 4; v++) acc[i][j][v] = 0.f;

    const int NK = 8;   // 512 / 64

    auto load_stage = [&](int s) {
        uint32_t sb = sbase + (s % NSTAGE) * STG;
        int k0 = s * 64;
#pragma unroll
        for (int i = 0; i < 4; i++) {
            int idx = tid + i * 256;          // 1024 chunks of 16B
            int r = idx >> 3, seg = idx & 7;
            int gr = row0 + r;
            int ok = (gr < M) ? 16 : 0;
            size_t off = (size_t)(gr < M ? gr : 0) * KP + k0 + seg * 8;
            uint32_t so = SWZ((uint32_t)(r * 128 + seg * 16));
            cpa16(sb + so,         Ah + off, ok);
            cpa16(sb + 16384 + so, Al + off, ok);
            size_t boff = (size_t)(col0 + r) * KP + k0 + seg * 8;
            cpa16(sb + 32768 + so, Bh + boff, 16);
            cpa16(sb + 49152 + so, Bl + boff, 16);
        }
    };

    load_stage(0); cpa_commit();
    load_stage(1); cpa_commit();

    for (int s = 0; s < NK; s++) {
        if (s + 2 < NK) load_stage(s + 2);
        cpa_commit();
        cpa_wait2();
        __syncthreads();

        uint32_t sb = sbase + (s % NSTAGE) * STG;
#pragma unroll
        for (int ks = 0; ks < 4; ks++) {
            uint32_t ah[4][4], al[4][4], bh[2][4], bl[2][4];
#pragma unroll
            for (int mt = 0; mt < 4; mt++) {
                int row = warp_m * 64 + mt * 16 + (lane & 15);
                int cb = ks * 32 + (lane >> 4) * 16;
                uint32_t ad = sb + SWZ((uint32_t)(row * 128 + cb));
                ldsm4(ah[mt], ad);
                ldsm4(al[mt], ad + 16384);
            }
#pragma unroll
            for (int bt = 0; bt < 2; bt++) {
                int g = lane >> 3, r = lane & 7;
                int n = warp_n * 32 + bt * 16 + (g >> 1) * 8 + r;
                int kb = ks * 32 + (g & 1) * 16;
                uint32_t bd = sb + 32768 + SWZ((uint32_t)(n * 128 + kb));
                ldsm4(bh[bt], bd);
                ldsm4(bl[bt], bd + 16384);
            }
#pragma unroll
            for (int mt = 0; mt < 4; mt++)
#pragma unroll
                for (int bt = 0; bt < 2; bt++) {
                    mma16816(acc[mt][bt * 2],     ah[mt], &bh[bt][0]);
                    mma16816(acc[mt][bt * 2],     ah[mt], &bl[bt][0]);
                    mma16816(acc[mt][bt * 2],     al[mt], &bh[bt][0]);
                    mma16816(acc[mt][bt * 2 + 1], ah[mt], &bh[bt][2]);
                    mma16816(acc[mt][bt * 2 + 1], ah[mt], &bl[bt][2]);
                    mma16816(acc[mt][bt * 2 + 1], al[mt], &bh[bt][2]);
                }
        }
        __syncthreads();
    }

    // ---- epilogue ----
#pragma unroll
    for (int mt = 0; mt < 4; mt++)
#pragma unroll
        for (int nt = 0; nt < 4; nt++) {
            int r = row0 + warp_m * 64 + mt * 16 + (lane >> 2);
            int c = col0 + warp_n * 32 + nt * 8 + (lane & 3) * 2;
            float b0 = bias ? __ldg(&bias[c]) : 0.f;
            float b1 = bias ? __ldg(&bias[c + 1]) : 0.f;
            if (r < M) {
                float2* p = (float2*)(C + (size_t)r * Ntot + c);
                *p = make_float2(acc[mt][nt][0] + b0, acc[mt][nt][1] + b1);
            }
            if (r + 8 < M) {
                float2* p = (float2*)(C + (size_t)(r + 8) * Ntot + c);
                *p = make_float2(acc[mt][nt][2] + b0, acc[mt][nt][3] + b1);
            }
        }
}

// --------------------------- CSR aggregation -------------------------------
// warp per node; software-pipelined edge loop (csr/dinv prefetch).
template <int H>
__global__ void k_agg(const float* __restrict__ xw, const float* __restrict__ bias,
                      float* __restrict__ out) {
    const int NV = H / 128;
    int warp = (blockIdx.x * blockDim.x + threadIdx.x) >> 5;
    int lane = threadIdx.x & 31;
    if (warp >= NN) return;
    float4 acc[NV];
#pragma unroll
    for (int j = 0; j < NV; j++) acc[j] = make_float4(0.f, 0.f, 0.f, 0.f);
    float dvi = g_dinv[warp];
    int e0 = g_off[warp], e1 = g_off[warp + 1];

    int s_nx = 0; float d_nx = 0.f;
    if (e0 < e1) { s_nx = __ldg(&g_csr[e0]); d_nx = __ldg(&g_dinv[s_nx]); }
    for (int e = e0; e < e1; e++) {
        int s = s_nx; float w = d_nx * dvi;
        if (e + 1 < e1) { s_nx = __ldg(&g_csr[e + 1]); d_nx = __ldg(&g_dinv[s_nx]); }
        const float4* row = (const float4*)(xw + (size_t)s * H);
#pragma unroll
        for (int j = 0; j < NV; j++) {
            float4 v = __ldg(&row[lane + 32 * j]);
            acc[j].x = fmaf(v.x, w, acc[j].x);
            acc[j].y = fmaf(v.y, w, acc[j].y);
            acc[j].z = fmaf(v.z, w, acc[j].z);
            acc[j].w = fmaf(v.w, w, acc[j].w);
        }
    }
    float4* orow = (float4*)(out + (size_t)warp * H);
    const float4* brow = (const float4*)bias;
#pragma unroll
    for (int j = 0; j < NV; j++) {
        float4 b = brow[lane + 32 * j];
        orow[lane + 32 * j] = make_float4(acc[j].x + b.x, acc[j].y + b.y,
                                          acc[j].z + b.z, acc[j].w + b.w);
    }
}

// --------------------------- BN + PairNorm ---------------------------------
template <int H>
__global__ void k_colstats(const float* __restrict__ h) {
    const int CPT = H / 256;
    int t = threadIdx.x;
    int r0 = blockIdx.x * 256;
    int rend = min(r0 + 256, NN);
    float s[CPT], sq[CPT];
#pragma unroll
    for (int c = 0; c < CPT; c++) { s[c] = 0.f; sq[c] = 0.f; }
    for (int r = r0; r < rend; r++) {
        const float* row = h + (size_t)r * H;
#pragma unroll
        for (int c = 0; c < CPT; c++) {
            float v = row[t + 256 * c];
            s[c] += v; sq[c] += v * v;
        }
    }
#pragma unroll
    for (int c = 0; c < CPT; c++) {
        atomicAdd(&g_colsum[t + 256 * c], s[c]);
        atomicAdd(&g_colsumsq[t + 256 * c], sq[c]);
    }
}
__global__ void k_bnfinal(const float* __restrict__ gamma, const float* __restrict__ beta) {
    int c = threadIdx.x;
    float inv_n = 1.f / (float)NN;
    float mu = g_colsum[c] * inv_n;
    float var = g_colsumsq[c] * inv_n - mu * mu;
    float a = rsqrtf(var + BN_EPSF) * gamma[c];
    g_bna[c] = a;
    g_bnb[c] = beta[c] - mu * a;
    g_colsum[c] = 0.f; g_colsumsq[c] = 0.f;
}
template <int H>
__global__ void k_bnapply(float* __restrict__ h) {
    const int CPT = H / 256;
    __shared__ float red[256];
    int t = threadIdx.x;
    int r0 = blockIdx.x * 256;
    int rend = min(r0 + 256, NN);
    float a[CPT], b[CPT], ps[CPT];
    float totsq = 0.f;
#pragma unroll
    for (int c = 0; c < CPT; c++) {
        a[c] = g_bna[t + 256 * c]; b[c] = g_bnb[t + 256 * c]; ps[c] = 0.f;
    }
    for (int r = r0; r < rend; r++) {
        float* row = h + (size_t)r * H;
#pragma unroll
        for (int c = 0; c < CPT; c++) {
            float v = row[t + 256 * c];
            float y = fmaxf(fmaf(v, a[c], b[c]), 0.f);
            row[t + 256 * c] = y;
            ps[c] += y;
            totsq = fmaf(y, y, totsq);
        }
    }
#pragma unroll
    for (int c = 0; c < CPT; c++) atomicAdd(&g_pnsum[t + 256 * c], ps[c]);
    red[t] = totsq; __syncthreads();
    for (int o = 128; o > 0; o >>= 1) {
        if (t < o) red[t] += red[t + o];
        __syncthreads();
    }
    if (t == 0) atomicAdd(&g_sumsqtot, red[0]);
}
__global__ void k_pnfinal(int H) {
    __shared__ float red[512];
    int c = threadIdx.x;
    float m = 0.f;
    if (c < H) { m = g_pnsum[c] / (float)NN; g_pnmean[c] = m; g_pnsum[c] = 0.f; }
    red[c] = m * m; __syncthreads();
    for (int o = 256; o > 0; o >>= 1) {
        if (c < o) red[c] += red[c + o];
        __syncthreads();
    }
    if (c == 0) {
        float meanrow = (g_sumsqtot - (float)NN * red[0]) / (float)NN;
        g_invd = 1.f / (sqrtf(fmaxf(meanrow, 0.f)) + PN_EPSF);
        g_sumsqtot = 0.f;
    }
}
template <int H>
__global__ void k_pnapply(float* __restrict__ h, const float* __restrict__ xp) {
    const int TOT4 = NN * H / 4;
    const int W4 = H / 4;
    float invd = g_invd;
    const float4* pm = (const float4*)g_pnmean;
    const float4* xp4 = (const float4*)xp;
    float4* h4 = (float4*)h;
    for (int i = blockIdx.x * blockDim.x + threadIdx.x; i < TOT4;
         i += gridDim.x * blockDim.x) {
        float4 m = pm[i % W4];
        float4 v = h4[i];
        float4 r = xp4[i];
        v.x = fmaf(v.x - m.x, invd, r.x);
        v.y = fmaf(v.y - m.y, invd, r.y);
        v.z = fmaf(v.z - m.z, invd, r.z);
        v.w = fmaf(v.w - m.w, invd, r.w);
        h4[i] = v;
    }
}
// layer-1 final: h1 -> bf16 hi/lo split directly (feeds layer-2 GEMMs)
__global__ void k_pnapply_split(const float* __restrict__ h, const float* __restrict__ xp) {
    float invd = g_invd;
    for (size_t i = (size_t)blockIdx.x * blockDim.x + threadIdx.x;
         i < (size_t)NN * H1D; i += (size_t)gridDim.x * blockDim.x) {
        int c = (int)(i & (H1D - 1));
        float v = fmaf(h[i] - g_pnmean[c], invd, xp[i]);
        bf16 hi = __float2bfloat16(v);
        bf16 lo = __float2bfloat16(v - __bfloat162float(hi));
        g_hh[i] = hi; g_hl[i] = lo;
    }
}

// ------------------------------ launcher -----------------------------------
extern "C" void kernel_launch(void* const* d_in, const int* in_sizes, int n_in,
                              void* d_out, int out_size) {
    const float* x   = (const float*)d_in[0];
    const int*   ei  = (const int*)  d_in[1];
    const float* W1  = (const float*)d_in[2];
    const float* b1  = (const float*)d_in[3];
    const float* ga1 = (const float*)d_in[4];
    const float* be1 = (const float*)d_in[5];
    const float* W2  = (const float*)d_in[6];
    const float* b2  = (const float*)d_in[7];
    const float* ga2 = (const float*)d_in[8];
    const float* be2 = (const float*)d_in[9];
    const float* P1w = (const float*)d_in[10];
    const float* P1b = (const float*)d_in[11];
    const float* P2w = (const float*)d_in[12];
    const float* P2b = (const float*)d_in[13];
    float* out = (float*)d_out;

    cudaFuncSetAttribute(k_gemm_mma, cudaFuncAttributeMaxDynamicSharedMemorySize,
                         GEMM_SMEM);

    float *xw, *xp, *h;
    cudaGetSymbolAddress((void**)&xw, g_xw);
    cudaGetSymbolAddress((void**)&xp, g_xp);
    cudaGetSymbolAddress((void**)&h,  g_h);
    bf16 *xh, *xl, *hh, *hl, *w1h, *w1l, *p1h, *p1l, *w2h, *w2l, *p2h, *p2l;
    cudaGetSymbolAddress((void**)&xh, g_xh);   cudaGetSymbolAddress((void**)&xl, g_xl);
    cudaGetSymbolAddress((void**)&hh, g_hh);   cudaGetSymbolAddress((void**)&hl, g_hl);
    cudaGetSymbolAddress((void**)&w1h, g_w1h); cudaGetSymbolAddress((void**)&w1l, g_w1l);
    cudaGetSymbolAddress((void**)&p1h, g_p1h); cudaGetSymbolAddress((void**)&p1l, g_p1l);
    cudaGetSymbolAddress((void**)&w2h, g_w2h); cudaGetSymbolAddress((void**)&w2l, g_w2l);
    cudaGetSymbolAddress((void**)&p2h, g_p2h); cudaGetSymbolAddress((void**)&p2l, g_p2l);

    const int* esrc = ei;
    const int* edst = ei + EE;

    const int MROWS = (NN + 127) / 128;   // 391

    // ---- conversions first so launch #5 (ncu -s 5) is the layer-1 GEMM ----
    k_splitw<<<(H1D * KP + 255) / 256, 256>>>(W1,  w1h, w1l, IND, H1D);    // 0
    k_splitw<<<(H1D * KP + 255) / 256, 256>>>(P1w, p1h, p1l, IND, H1D);    // 1
    k_splitw<<<(H2D * KP + 255) / 256, 256>>>(W2,  w2h, w2l, H1D, H2D);    // 2
    k_splitw<<<(H2D * KP + 255) / 256, 256>>>(P2w, p2h, p2l, H1D, H2D);    // 3
    k_splitx<<<(int)(((size_t)NN * KP + 255) / 256), 256>>>(x);            // 4

    // ---- layer-1 fused GEMM (W + P in one launch) ----                  // 5
    k_gemm_mma<<<dim3(2 * (H1D / 128), MROWS), 256, GEMM_SMEM>>>(
        xh, xl, w1h, w1l, p1h, p1l, P1b, xw, xp, NN, H1D);

    // ---- graph prep (ordered before agg) ----
    k_init <<<(NN + 255) / 256, 256>>>();
    k_count<<<(EE + 255) / 256, 256>>>(edst);
    k_dinv <<<(NN + 255) / 256, 256>>>();
    k_scan1<<<SCAN_NB, SCAN_CH>>>();
    k_scan2<<<1, 1024>>>();
    k_scan3<<<SCAN_NB, SCAN_CH>>>();
    k_fill <<<(TOTE + 255) / 256, 256>>>(esrc, edst);

    // ---- layer 1 rest ----
    k_agg<H1D><<<(NN + 7) / 8, 256>>>(xw, b1, h);
    k_colstats<H1D><<<(NN + 255) / 256, 256>>>(h);
    k_bnfinal<<<1, H1D>>>(ga1, be1);
    k_bnapply<H1D><<<(NN + 255) / 256, 256>>>(h);
    k_pnfinal<<<1, 512>>>(H1D);
    k_pnapply_split<<<2048, 256>>>(h, xp);

    // ---- layer 2 ----
    k_gemm_mma<<<dim3(2 * (H2D / 128), MROWS), 256, GEMM_SMEM>>>(
        hh, hl, w2h, w2l, p2h, p2l, P2b, xw, xp, NN, H2D);
    k_agg<H2D><<<(NN + 7) / 8, 256>>>(xw, b2, out);
    k_colstats<H2D><<<(NN + 255) / 256, 256>>>(out);
    k_bnfinal<<<1, H2D>>>(ga2, be2);
    k_bnapply<H2D><<<(NN + 255) / 256, 256>>>(out);
    k_pnfinal<<<1, 512>>>(H2D);
    k_pnapply<H2D><<<2048, 256>>>(out, xp);
}